// round 3
// baseline (speedup 1.0000x reference)
#include <cuda_runtime.h>
#include <math.h>

#define BB   2
#define TT   2048
#define BT   4096
#define DIMC 1024
#define NH   16
#define HD   64
#define HID  4096
#define EPSV 1e-6f

// ---------------- scratch ----------------------------------------------------
__device__ float g_xn[BT * DIMC];
__device__ float g_q [BT * DIMC];
__device__ float g_k [BT * DIMC];
__device__ float g_v [BT * DIMC];
__device__ float g_ao[BT * DIMC];
__device__ float g_x1[BT * DIMC];
__device__ float g_h [BT * HID];

// ---------------- tf32 helpers -----------------------------------------------
__device__ __forceinline__ unsigned f2tf(float f) {
    unsigned u;
    asm("cvt.rna.tf32.f32 %0, %1;" : "=r"(u) : "f"(f));
    return u;
}

__device__ __forceinline__ void mma8(float* d, const unsigned* a, const unsigned* b) {
    asm volatile(
        "mma.sync.aligned.m16n8k8.row.col.f32.tf32.tf32.f32 "
        "{%0,%1,%2,%3}, {%4,%5,%6,%7}, {%8,%9}, {%0,%1,%2,%3};"
        : "+f"(d[0]), "+f"(d[1]), "+f"(d[2]), "+f"(d[3])
        : "r"(a[0]), "r"(a[1]), "r"(a[2]), "r"(a[3]), "r"(b[0]), "r"(b[1]));
}

// ---------------- RMSNorm ----------------------------------------------------
__global__ void rmsnorm_kernel(const float* __restrict__ x,
                               const float* __restrict__ g,
                               float* __restrict__ y) {
    int row = blockIdx.x;
    int tid = threadIdx.x;
    const float* xr = x + (size_t)row * DIMC;
    float4 xv = *(const float4*)(xr + tid * 4);
    float s = xv.x * xv.x + xv.y * xv.y + xv.z * xv.z + xv.w * xv.w;
    #pragma unroll
    for (int off = 16; off; off >>= 1) s += __shfl_xor_sync(0xFFFFFFFFu, s, off);
    __shared__ float ws[8];
    __shared__ float snorm;
    if ((tid & 31) == 0) ws[tid >> 5] = s;
    __syncthreads();
    if (tid == 0) {
        float t = 0.f;
        #pragma unroll
        for (int i = 0; i < 8; i++) t += ws[i];
        snorm = rsqrtf(t * (1.0f / DIMC) + EPSV);
    }
    __syncthreads();
    float n = snorm;
    float4 gv = *(const float4*)(g + tid * 4);
    float4 ov;
    ov.x = xv.x * n * gv.x;
    ov.y = xv.y * n * gv.y;
    ov.z = xv.z * n * gv.z;
    ov.w = xv.w * n * gv.w;
    *(float4*)(y + (size_t)row * DIMC + tid * 4) = ov;
}

// ---------------- TF32 GEMM 128x128, K-tile 32, fragment smem, 2-stage --------
// As frag layout: slot addr = ((rb*4+kk)*32 + g*4 + tgs)*4 + e ; tgs=(tg+(g>>1))&3
//   e: [ (g,tg), (g+8,tg), (g,tg+4), (g+8,tg+4) ]
// Bs frag layout: ((kk*16+nb)*36 + g*4 + tgb)*2 + e ; tgb=(tg+nb)&3 ; e: [k=tg, k=tg+4]
#define G_STAGE 8704                   // 4096 (A) + 4608 (B) unsigned
#define G_SMEM  (2 * G_STAGE * 4)

__global__ __launch_bounds__(256, 2)
void gemm_tf32(const float* __restrict__ A, const float* __restrict__ B,
               float* __restrict__ C, const float* __restrict__ res,
               int M, int N, int K, int do_silu) {
    extern __shared__ unsigned smg[];
    const int tid  = threadIdx.x;
    const int lane = tid & 31, warp = tid >> 5;
    const int lg = lane >> 2, ltg = lane & 3;
    const int wm = warp >> 2, wn = warp & 3;
    const int bm0 = blockIdx.y * 128, bn0 = blockIdx.x * 128;
    const int rsw = (lg >> 1) & 3;

    // A loader: rows (arb*16+ag, +8), cols akk*8..+7
    const int ag = tid & 7, akk = (tid >> 3) & 3, arb = tid >> 5;
    const float* Ap0 = A + (size_t)(bm0 + arb * 16 + ag) * K + akk * 8;
    const float* Ap1 = Ap0 + (size_t)8 * K;
    const int a_sbase = (arb * 4 + akk) * 128 + ag * 16;
    const int a_sw = (ag >> 1) & 3;

    // B loader: rows (bkk*8+btg, +4), cols bn4*4..+3 ; bkk = bk0 + 2i
    const int btg = tid & 3, bn4 = (tid >> 2) & 31, bk0 = tid >> 7;
    const int bnb = bn4 >> 1, bgb = (bn4 & 1) * 4;
    const int btgb = (btg + bnb) & 3;
    const float* Bp0 = B + (size_t)(bk0 * 8 + btg) * N + bn0 + bn4 * 4;
    const float* Bp1 = Bp0 + (size_t)16 * N;

    float acc[4][4][4];
    #pragma unroll
    for (int mt = 0; mt < 4; mt++)
        #pragma unroll
        for (int nt = 0; nt < 4; nt++)
            #pragma unroll
            for (int r = 0; r < 4; r++) acc[mt][nt][r] = 0.f;

    float a0[4], a1[4], a2[4], a3[4];
    float bl0[4], bh0[4], bl1[4], bh1[4];

    auto LOADG = [&](int kt) {
        size_t ko = (size_t)kt * 32;
        *(float4*)a0 = *(const float4*)(Ap0 + ko);
        *(float4*)a1 = *(const float4*)(Ap0 + ko + 4);
        *(float4*)a2 = *(const float4*)(Ap1 + ko);
        *(float4*)a3 = *(const float4*)(Ap1 + ko + 4);
        size_t kob = ko * N;
        *(float4*)bl0 = *(const float4*)(Bp0 + kob);
        *(float4*)bh0 = *(const float4*)(Bp0 + kob + (size_t)4 * N);
        *(float4*)bl1 = *(const float4*)(Bp1 + kob);
        *(float4*)bh1 = *(const float4*)(Bp1 + kob + (size_t)4 * N);
    };
    auto STORES = [&](unsigned* As, unsigned* Bs) {
        #pragma unroll
        for (int t = 0; t < 4; t++) {
            int tgs = (t + a_sw) & 3;
            uint4 v;
            v.x = f2tf(a0[t]); v.y = f2tf(a2[t]);
            v.z = f2tf(a1[t]); v.w = f2tf(a3[t]);
            *(uint4*)&As[a_sbase + tgs * 4] = v;
        }
        #pragma unroll
        for (int j = 0; j < 4; j++) {
            uint2 v0, v1;
            v0.x = f2tf(bl0[j]); v0.y = f2tf(bh0[j]);
            v1.x = f2tf(bl1[j]); v1.y = f2tf(bh1[j]);
            int sl = ((bnb) * 36 + (bgb + j) * 4 + btgb) * 2;
            *(uint2*)&Bs[(bk0 * 16) * 72 + sl] = v0;
            *(uint2*)&Bs[((bk0 + 2) * 16) * 72 + sl] = v1;
        }
    };

    LOADG(0);
    STORES(smg, smg + 4096);
    __syncthreads();

    const int nkt = K >> 5;
    for (int kt = 0; kt < nkt; kt++) {
        unsigned* As = smg + (kt & 1) * G_STAGE;
        unsigned* Bs = As + 4096;
        bool pf = (kt + 1 < nkt);
        if (pf) LOADG(kt + 1);

        #pragma unroll
        for (int kk = 0; kk < 4; kk++) {
            uint4 af[4]; uint2 bf[4];
            #pragma unroll
            for (int mt = 0; mt < 4; mt++)
                af[mt] = *(const uint4*)&As[((wm * 4 + mt) * 4 + kk) * 128
                                            + lg * 16 + ((ltg + rsw) & 3) * 4];
            #pragma unroll
            for (int nt = 0; nt < 4; nt++) {
                int nb = wn * 4 + nt;
                bf[nt] = *(const uint2*)&Bs[((kk * 16 + nb) * 36 + lg * 4
                                             + ((ltg + nb) & 3)) * 2];
            }
            #pragma unroll
            for (int mt = 0; mt < 4; mt++)
                #pragma unroll
                for (int nt = 0; nt < 4; nt++)
                    mma8(acc[mt][nt], (const unsigned*)&af[mt], (const unsigned*)&bf[nt]);
        }
        if (pf) {
            unsigned* As2 = smg + ((kt + 1) & 1) * G_STAGE;
            STORES(As2, As2 + 4096);
        }
        __syncthreads();
    }

    // epilogue
    #pragma unroll
    for (int mt = 0; mt < 4; mt++) {
        #pragma unroll
        for (int half = 0; half < 2; half++) {
            int r = bm0 + wm * 64 + mt * 16 + lg + half * 8;
            #pragma unroll
            for (int nt = 0; nt < 4; nt++) {
                int c = bn0 + wn * 32 + nt * 8 + 2 * ltg;
                float v0 = acc[mt][nt][half * 2 + 0];
                float v1 = acc[mt][nt][half * 2 + 1];
                if (do_silu) {
                    v0 = v0 / (1.f + __expf(-v0));
                    v1 = v1 / (1.f + __expf(-v1));
                }
                if (res) {
                    float2 rv = *(const float2*)(res + (size_t)r * N + c);
                    v0 += rv.x; v1 += rv.y;
                }
                *(float2*)(C + (size_t)r * N + c) = make_float2(v0, v1);
            }
        }
    }
}

// ---------------- Flash attention, BM=128, fragment smem ----------------------
// Kf/Vf: B-frag layout ((kk*8+nt)*36 + g*4 + tgx)*2 + e
//   Kf: pair along head-dim (c=tg, c=tg+4), g = key row & 7, tgx=(tg+kk)&3
//   Vf: pair along key-row (r=tg, r=tg+4), g = col & 7,     tgx=(tg+nt)&3
// Pf: A-frag layout ((warp*8+kt)*32 + g*4 + ((tg+(g>>1))&3))*4 + e
#define AKV 4608
#define APF 8192
#define A_SMEM ((2 * AKV + APF) * 4)

__global__ __launch_bounds__(256, 2)
void attn_tf32(const float* __restrict__ Q, const float* __restrict__ K,
               const float* __restrict__ V, float* __restrict__ O) {
    extern __shared__ unsigned sma[];
    unsigned* Kf = sma;
    unsigned* Vf = sma + AKV;
    unsigned* Pf = sma + 2 * AKV;

    int bh = blockIdx.x, qt = blockIdx.y;
    int b = bh >> 4, h = bh & 15;
    int q0 = qt * 128;
    int tid = threadIdx.x, warp = tid >> 5, lane = tid & 31;
    int lg = lane >> 2, ltg = lane & 3;
    int r0l = warp * 16 + lg;
    int r0g = q0 + r0l, r1g = r0g + 8;
    int rmax = q0 + warp * 16 + 15;
    int rsw = (lg >> 1) & 3;

    const float* Qb = Q + ((size_t)(b * TT + q0)) * DIMC + h * HD;
    const float* Kb = K + ((size_t)(b * TT)) * DIMC + h * HD;
    const float* Vb = V + ((size_t)(b * TT)) * DIMC + h * HD;

    unsigned qa[8][4];
    #pragma unroll
    for (int kk = 0; kk < 8; kk++) {
        qa[kk][0] = f2tf(Qb[(size_t)r0l * DIMC + kk * 8 + ltg] * 0.125f);
        qa[kk][1] = f2tf(Qb[(size_t)(r0l + 8) * DIMC + kk * 8 + ltg] * 0.125f);
        qa[kk][2] = f2tf(Qb[(size_t)r0l * DIMC + kk * 8 + ltg + 4] * 0.125f);
        qa[kk][3] = f2tf(Qb[(size_t)(r0l + 8) * DIMC + kk * 8 + ltg + 4] * 0.125f);
    }

    float oacc[8][4];
    #pragma unroll
    for (int nt = 0; nt < 8; nt++)
        #pragma unroll
        for (int r = 0; r < 4; r++) oacc[nt][r] = 0.f;
    float m0 = -1e30f, m1 = -1e30f, l0 = 0.f, l1 = 0.f;

    // loader mappings
    int kr = tid >> 2;                       // K: key row 0..63
    int knt = kr >> 3, kg = kr & 7;
    int vtg = tid & 3, vc4 = (tid >> 2) & 15, vkt0 = tid >> 6;
    int vnb = vc4 >> 1, vgb = (vc4 & 1) * 4;

    int send = q0 + 64;
    for (int s0 = 0; s0 <= send; s0 += 64) {
        // ---- load K tile ----
        #pragma unroll
        for (int i = 0; i < 2; i++) {
            int kk = (tid & 3) + 4 * i;
            const float* p = Kb + (size_t)(s0 + kr) * DIMC + kk * 8;
            float lo[4], hi[4];
            *(float4*)lo = *(const float4*)p;
            *(float4*)hi = *(const float4*)(p + 4);
            #pragma unroll
            for (int t = 0; t < 4; t++) {
                uint2 v; v.x = f2tf(lo[t]); v.y = f2tf(hi[t]);
                *(uint2*)&Kf[((kk * 8 + knt) * 36 + kg * 4 + ((t + kk) & 3)) * 2] = v;
            }
        }
        // ---- load V tile ----
        #pragma unroll
        for (int i = 0; i < 2; i++) {
            int kt = vkt0 + 4 * i;
            const float* p = Vb + (size_t)(s0 + kt * 8 + vtg) * DIMC + vc4 * 4;
            float lo[4], hi[4];
            *(float4*)lo = *(const float4*)p;
            *(float4*)hi = *(const float4*)(p + (size_t)4 * DIMC);
            #pragma unroll
            for (int j = 0; j < 4; j++) {
                uint2 v; v.x = f2tf(lo[j]); v.y = f2tf(hi[j]);
                *(uint2*)&Vf[((kt * 8 + vnb) * 36 + (vgb + j) * 4
                              + ((vtg + vnb) & 3)) * 2] = v;
            }
        }
        __syncthreads();

        if (s0 <= rmax) {
            // S = Q K^T
            float sc[8][4];
            #pragma unroll
            for (int nt = 0; nt < 8; nt++)
                #pragma unroll
                for (int r = 0; r < 4; r++) sc[nt][r] = 0.f;
            #pragma unroll
            for (int kk = 0; kk < 8; kk++) {
                #pragma unroll
                for (int nt = 0; nt < 8; nt++) {
                    uint2 bf = *(const uint2*)&Kf[((kk * 8 + nt) * 36 + lg * 4
                                                   + ((ltg + kk) & 3)) * 2];
                    mma8(sc[nt], qa[kk], (const unsigned*)&bf);
                }
            }

            // causal mask
            if (s0 + 63 > r0g) {
                #pragma unroll
                for (int nt = 0; nt < 8; nt++) {
                    int j = s0 + nt * 8 + 2 * ltg;
                    if (j     > r0g) sc[nt][0] = -1e30f;
                    if (j + 1 > r0g) sc[nt][1] = -1e30f;
                    if (j     > r1g) sc[nt][2] = -1e30f;
                    if (j + 1 > r1g) sc[nt][3] = -1e30f;
                }
            }

            // online softmax
            float mx0 = -1e30f, mx1 = -1e30f;
            #pragma unroll
            for (int nt = 0; nt < 8; nt++) {
                mx0 = fmaxf(mx0, fmaxf(sc[nt][0], sc[nt][1]));
                mx1 = fmaxf(mx1, fmaxf(sc[nt][2], sc[nt][3]));
            }
            mx0 = fmaxf(mx0, __shfl_xor_sync(0xFFFFFFFFu, mx0, 1));
            mx0 = fmaxf(mx0, __shfl_xor_sync(0xFFFFFFFFu, mx0, 2));
            mx1 = fmaxf(mx1, __shfl_xor_sync(0xFFFFFFFFu, mx1, 1));
            mx1 = fmaxf(mx1, __shfl_xor_sync(0xFFFFFFFFu, mx1, 2));
            float mn0 = fmaxf(m0, mx0), mn1 = fmaxf(m1, mx1);
            float al0 = __expf(m0 - mn0), al1 = __expf(m1 - mn1);
            float s0r = 0.f, s1r = 0.f;
            #pragma unroll
            for (int nt = 0; nt < 8; nt++) {
                sc[nt][0] = __expf(sc[nt][0] - mn0);
                sc[nt][1] = __expf(sc[nt][1] - mn0);
                sc[nt][2] = __expf(sc[nt][2] - mn1);
                sc[nt][3] = __expf(sc[nt][3] - mn1);
                s0r += sc[nt][0] + sc[nt][1];
                s1r += sc[nt][2] + sc[nt][3];
            }
            s0r += __shfl_xor_sync(0xFFFFFFFFu, s0r, 1);
            s0r += __shfl_xor_sync(0xFFFFFFFFu, s0r, 2);
            s1r += __shfl_xor_sync(0xFFFFFFFFu, s1r, 1);
            s1r += __shfl_xor_sync(0xFFFFFFFFu, s1r, 2);
            l0 = l0 * al0 + s0r;
            l1 = l1 * al1 + s1r;
            m0 = mn0; m1 = mn1;
            #pragma unroll
            for (int nt = 0; nt < 8; nt++) {
                oacc[nt][0] *= al0; oacc[nt][1] *= al0;
                oacc[nt][2] *= al1; oacc[nt][3] *= al1;
            }

            // P -> Pf (A-frag layout)
            int ci0 = 2 * ltg, ci1 = ci0 + 1;
            int sl0 = ((ci0 & 3) + rsw) & 3, sl1 = ((ci1 & 3) + rsw) & 3;
            int e0 = (ci0 >> 2) * 2, e1 = (ci1 >> 2) * 2;
            #pragma unroll
            for (int nt = 0; nt < 8; nt++) {
                int base = (warp * 8 + nt) * 32 + lg * 4;
                uint2 v0; v0.x = f2tf(sc[nt][0]); v0.y = f2tf(sc[nt][2]);
                uint2 v1; v1.x = f2tf(sc[nt][1]); v1.y = f2tf(sc[nt][3]);
                *(uint2*)&Pf[(base + sl0) * 4 + e0] = v0;
                *(uint2*)&Pf[(base + sl1) * 4 + e1] = v1;
            }
            __syncwarp();

            // O += P @ V
            #pragma unroll
            for (int kt = 0; kt < 8; kt++) {
                uint4 pa = *(const uint4*)&Pf[((warp * 8 + kt) * 32 + lg * 4
                                               + ((ltg + rsw) & 3)) * 4];
                #pragma unroll
                for (int nt = 0; nt < 8; nt++) {
                    uint2 bf = *(const uint2*)&Vf[((kt * 8 + nt) * 36 + lg * 4
                                                   + ((ltg + nt) & 3)) * 2];
                    mma8(oacc[nt], (const unsigned*)&pa, (const unsigned*)&bf);
                }
            }
        }
        __syncthreads();
    }

    float il0 = 1.f / l0, il1 = 1.f / l1;
    float* Ob = O + ((size_t)(b * TT + q0 + r0l)) * DIMC + h * HD;
    #pragma unroll
    for (int nt = 0; nt < 8; nt++) {
        *(float2*)(Ob + nt * 8 + 2 * ltg) =
            make_float2(oacc[nt][0] * il0, oacc[nt][1] * il0);
        *(float2*)(Ob + (size_t)8 * DIMC + nt * 8 + 2 * ltg) =
            make_float2(oacc[nt][2] * il1, oacc[nt][3] * il1);
    }
}

// ---------------- launcher ----------------------------------------------------
extern "C" void kernel_launch(void* const* d_in, const int* in_sizes, int n_in,
                              void* d_out, int out_size) {
    const float* x  = (const float*)d_in[0];
    const float* wq = (const float*)d_in[2];
    const float* wk = (const float*)d_in[3];
    const float* wv = (const float*)d_in[4];
    const float* wo = (const float*)d_in[5];
    const float* w1 = (const float*)d_in[6];
    const float* w2 = (const float*)d_in[7];
    const float* ga = (const float*)d_in[8];
    const float* gf = (const float*)d_in[9];
    float* out = (float*)d_out;

    float *xn, *q, *k, *v, *ao, *x1, *hb;
    cudaGetSymbolAddress((void**)&xn, g_xn);
    cudaGetSymbolAddress((void**)&q,  g_q);
    cudaGetSymbolAddress((void**)&k,  g_k);
    cudaGetSymbolAddress((void**)&v,  g_v);
    cudaGetSymbolAddress((void**)&ao, g_ao);
    cudaGetSymbolAddress((void**)&x1, g_x1);
    cudaGetSymbolAddress((void**)&hb, g_h);

    cudaFuncSetAttribute(gemm_tf32,
                         cudaFuncAttributeMaxDynamicSharedMemorySize, G_SMEM);
    cudaFuncSetAttribute(attn_tf32,
                         cudaFuncAttributeMaxDynamicSharedMemorySize, A_SMEM);

    dim3 gN1(DIMC / 128, BT / 128);   // (8, 32)
    dim3 gN4(HID  / 128, BT / 128);   // (32, 32)

    rmsnorm_kernel<<<BT, 256>>>(x, ga, xn);
    gemm_tf32<<<gN1, 256, G_SMEM>>>(xn, wq, q, nullptr, BT, DIMC, DIMC, 0);
    gemm_tf32<<<gN1, 256, G_SMEM>>>(xn, wk, k, nullptr, BT, DIMC, DIMC, 0);
    gemm_tf32<<<gN1, 256, G_SMEM>>>(xn, wv, v, nullptr, BT, DIMC, DIMC, 0);
    attn_tf32<<<dim3(BB * NH, TT / 128), 256, A_SMEM>>>(q, k, v, ao);
    gemm_tf32<<<gN1, 256, G_SMEM>>>(ao, wo, x1, x, BT, DIMC, DIMC, 0);
    rmsnorm_kernel<<<BT, 256>>>(x1, gf, xn);
    gemm_tf32<<<gN4, 256, G_SMEM>>>(xn, w1, hb, nullptr, BT, HID, DIMC, 1);
    gemm_tf32<<<gN1, 256, G_SMEM>>>(hb, w2, out, x1, BT, DIMC, HID, 0);
}

// round 5
// speedup vs baseline: 1.5037x; 1.5037x over previous
#include <cuda_runtime.h>
#include <math.h>
#include <cstdint>

#define BB   2
#define TT   2048
#define BT   4096
#define DIMC 1024
#define NH   16
#define HD   64
#define HID  4096
#define EPSV 1e-6f

// ---------------- scratch ----------------------------------------------------
__device__ float g_xn[BT * DIMC];
__device__ float g_q [BT * DIMC];
__device__ float g_k [BT * DIMC];
__device__ float g_v [BT * DIMC];
__device__ float g_ao[BT * DIMC];
__device__ float g_x1[BT * DIMC];
__device__ float g_h [BT * HID];

// ---------------- helpers -----------------------------------------------------
__device__ __forceinline__ unsigned f2tf(float f) {
    unsigned u;
    asm("cvt.rna.tf32.f32 %0, %1;" : "=r"(u) : "f"(f));
    return u;
}
__device__ __forceinline__ unsigned tf32bits(unsigned x) {
    unsigned u;
    asm("cvt.rna.tf32.f32 %0, %1;" : "=r"(u) : "f"(__uint_as_float(x)));
    return u;
}
__device__ __forceinline__ uint32_t smem_u32(const void* p) {
    uint32_t a;
    asm("{ .reg .u64 t; cvta.to.shared.u64 t, %1; cvt.u32.u64 %0, t; }"
        : "=r"(a) : "l"(p));
    return a;
}
__device__ __forceinline__ void mma8(float* d, const unsigned* a, const unsigned* b) {
    asm volatile(
        "mma.sync.aligned.m16n8k8.row.col.f32.tf32.tf32.f32 "
        "{%0,%1,%2,%3}, {%4,%5,%6,%7}, {%8,%9}, {%0,%1,%2,%3};"
        : "+f"(d[0]), "+f"(d[1]), "+f"(d[2]), "+f"(d[3])
        : "r"(a[0]), "r"(a[1]), "r"(a[2]), "r"(a[3]), "r"(b[0]), "r"(b[1]));
}
__device__ __forceinline__ void ldsm4(uint32_t addr, unsigned* r) {
    asm volatile("ldmatrix.sync.aligned.m8n8.x4.shared.b16 {%0,%1,%2,%3}, [%4];"
        : "=r"(r[0]), "=r"(r[1]), "=r"(r[2]), "=r"(r[3]) : "r"(addr));
}
__device__ __forceinline__ void cpasync16(uint32_t dst, const float* src) {
    asm volatile("cp.async.cg.shared.global [%0], [%1], 16;"
        :: "r"(dst), "l"(__cvta_generic_to_global(src)));
}
#define CP_COMMIT asm volatile("cp.async.commit_group;" ::: "memory")
#define CP_WAIT0  asm volatile("cp.async.wait_group 0;" ::: "memory")

// ---------------- RMSNorm ----------------------------------------------------
__global__ void rmsnorm_kernel(const float* __restrict__ x,
                               const float* __restrict__ g,
                               float* __restrict__ y) {
    int row = blockIdx.x;
    int tid = threadIdx.x;
    const float* xr = x + (size_t)row * DIMC;
    float4 xv = *(const float4*)(xr + tid * 4);
    float s = xv.x * xv.x + xv.y * xv.y + xv.z * xv.z + xv.w * xv.w;
    #pragma unroll
    for (int off = 16; off; off >>= 1) s += __shfl_xor_sync(0xFFFFFFFFu, s, off);
    __shared__ float ws[8];
    __shared__ float snorm;
    if ((tid & 31) == 0) ws[tid >> 5] = s;
    __syncthreads();
    if (tid == 0) {
        float t = 0.f;
        #pragma unroll
        for (int i = 0; i < 8; i++) t += ws[i];
        snorm = rsqrtf(t * (1.0f / DIMC) + EPSV);
    }
    __syncthreads();
    float n = snorm;
    float4 gv = *(const float4*)(g + tid * 4);
    float4 ov;
    ov.x = xv.x * n * gv.x;
    ov.y = xv.y * n * gv.y;
    ov.z = xv.z * n * gv.z;
    ov.w = xv.w * n * gv.w;
    *(float4*)(y + (size_t)row * DIMC + tid * 4) = ov;
}

// ---------------- TF32 GEMM 128x128, K-chunk 32, ldmatrix + cp.async ----------
// smem stages: A(raw fp32) [128 rows][32 k] SW128, B(tf32, n-major) [128 n][32 k] SW128
#define GS_A(s) ((s) * 16384)
#define GS_B(s) (32768 + (s) * 16384)
#define G_SMEM  65536
#define SWZ(row, off) ((row) * 128 + ((off) ^ (((row) & 7) << 4)))

__global__ __launch_bounds__(256, 2)
void gemm_tf32(const float* __restrict__ A, const float* __restrict__ B,
               float* __restrict__ C, const float* __restrict__ res,
               int M, int N, int K, int do_silu) {
    extern __shared__ char smc[];
    const uint32_t sbase = smem_u32(smc);
    const int tid = threadIdx.x;
    const int warp = tid >> 5, lane = tid & 31;
    const int lg = lane >> 2, ltg = lane & 3;
    const int wm = warp >> 2, wn = warp & 3;
    const int bm0 = blockIdx.y * 128, bn0 = blockIdx.x * 128;

    // A cp.async mapping: row = (tid>>3)+32i, k4 = tid&7
    const int a_row = tid >> 3, a_k4 = tid & 7;
    const float* Agp = A + (size_t)(bm0 + a_row) * K + a_k4 * 4;

    // B loader: n = tid&127, k4 = (tid>>7) + 2i
    const int b_n = tid & 127, b_k4a = tid >> 7;
    const float* Bgp = B + (size_t)(b_k4a * 4) * N + bn0 + b_n;

    // fragment address precompute
    const int mat = lane >> 3, mrow = lane & 7;
    const int ah16 = (mat >> 1) << 4;        // A k-half from matrix idx
    const int bh16 = (mat & 1) << 4;         // B k-half from matrix idx
    int aoff[4], boff[4];
    #pragma unroll
    for (int mt = 0; mt < 4; mt++) {
        int row = wm * 64 + mt * 16 + (mat & 1) * 8 + mrow;
        aoff[mt] = row * 128 + (ah16 ^ ((row & 7) << 4));
    }
    #pragma unroll
    for (int p = 0; p < 2; p++) {
        int n = (wn * 4 + p * 2 + (mat >> 1)) * 8 + mrow;
        boff[p] = n * 128 + (bh16 ^ ((n & 7) << 4));
    }

    float acc[4][4][4];
    #pragma unroll
    for (int mt = 0; mt < 4; mt++)
        #pragma unroll
        for (int nt = 0; nt < 4; nt++)
            #pragma unroll
            for (int r = 0; r < 4; r++) acc[mt][nt][r] = 0.f;

    float bst[4][4];

    auto loadA = [&](int kt, int buf) {
        uint32_t dst = sbase + GS_A(buf);
        #pragma unroll
        for (int i = 0; i < 4; i++) {
            int row = a_row + i * 32;
            cpasync16(dst + SWZ(row, a_k4 * 16), Agp + (size_t)i * 32 * K + kt * 32);
        }
    };
    auto ldgB = [&](int kt) {
        #pragma unroll
        for (int i = 0; i < 4; i++) {
            const float* p = Bgp + (size_t)(kt * 32 + i * 8) * N;
            bst[i][0] = p[0];
            bst[i][1] = p[(size_t)N];
            bst[i][2] = p[(size_t)2 * N];
            bst[i][3] = p[(size_t)3 * N];
        }
    };
    auto stsB = [&](int buf) {
        char* bb = smc + GS_B(buf);
        #pragma unroll
        for (int i = 0; i < 4; i++) {
            int k4 = b_k4a + 2 * i;
            uint4 u;
            u.x = f2tf(bst[i][0]); u.y = f2tf(bst[i][1]);
            u.z = f2tf(bst[i][2]); u.w = f2tf(bst[i][3]);
            *(uint4*)(bb + SWZ(b_n, k4 * 16)) = u;
        }
    };

    loadA(0, 0);
    CP_COMMIT;
    ldgB(0);
    stsB(0);
    CP_WAIT0;
    __syncthreads();

    const int nkt = K >> 5;
    for (int kt = 0; kt < nkt; kt++) {
        int buf = kt & 1;
        bool pf = (kt + 1 < nkt);
        if (pf) {
            loadA(kt + 1, buf ^ 1);
            CP_COMMIT;
            ldgB(kt + 1);
        }
        uint32_t sa = sbase + GS_A(buf);
        uint32_t sb = sbase + GS_B(buf);
        #pragma unroll
        for (int kk = 0; kk < 4; kk++) {
            unsigned af[4][4], bf[4][2];
            #pragma unroll
            for (int mt = 0; mt < 4; mt++) {
                ldsm4(sa + aoff[mt] + ((kk * 32) ^ 0), af[mt]);
                // note: kk*32 only touches bits 5-6, untouched by swizzle xor (bits 4-6
                // xor uses row bits; adding kk*32 is safe since aoff bits 5-6 of the
                // xored half-offset may carry — recompute exactly instead:
            }
            // exact addresses (recompute to keep swizzle correct across kk)
            #pragma unroll
            for (int mt = 0; mt < 4; mt++) {
                int row = wm * 64 + mt * 16 + (mat & 1) * 8 + mrow;
                uint32_t ad = sa + row * 128 + ((kk * 32 + ah16) ^ ((row & 7) << 4));
                ldsm4(ad, af[mt]);
                af[mt][0] = tf32bits(af[mt][0]);
                af[mt][1] = tf32bits(af[mt][1]);
                af[mt][2] = tf32bits(af[mt][2]);
                af[mt][3] = tf32bits(af[mt][3]);
            }
            #pragma unroll
            for (int p = 0; p < 2; p++) {
                int n = (wn * 4 + p * 2 + (mat >> 1)) * 8 + mrow;
                uint32_t bd = sb + n * 128 + ((kk * 32 + bh16) ^ ((n & 7) << 4));
                unsigned r[4];
                ldsm4(bd, r);
                bf[p * 2][0] = r[0];     bf[p * 2][1] = r[1];
                bf[p * 2 + 1][0] = r[2]; bf[p * 2 + 1][1] = r[3];
            }
            #pragma unroll
            for (int mt = 0; mt < 4; mt++)
                #pragma unroll
                for (int nt = 0; nt < 4; nt++)
                    mma8(acc[mt][nt], af[mt], bf[nt]);
        }
        if (pf) {
            stsB(buf ^ 1);
            CP_WAIT0;
        }
        __syncthreads();
    }

    // epilogue: rows wm*64+mt*16+lg(+8), cols wn*32+nt*8+2*ltg
    #pragma unroll
    for (int mt = 0; mt < 4; mt++) {
        #pragma unroll
        for (int half = 0; half < 2; half++) {
            int r = bm0 + wm * 64 + mt * 16 + lg + half * 8;
            #pragma unroll
            for (int nt = 0; nt < 4; nt++) {
                int c = bn0 + wn * 32 + nt * 8 + 2 * ltg;
                float v0 = acc[mt][nt][half * 2 + 0];
                float v1 = acc[mt][nt][half * 2 + 1];
                if (do_silu) {
                    v0 = v0 / (1.f + __expf(-v0));
                    v1 = v1 / (1.f + __expf(-v1));
                }
                if (res) {
                    float2 rv = *(const float2*)(res + (size_t)r * N + c);
                    v0 += rv.x; v1 += rv.y;
                }
                *(float2*)(C + (size_t)r * N + c) = make_float2(v0, v1);
            }
        }
    }
}

// ---------------- Flash attention (round-2 version) ----------------------------
#define AST 68
#define ATT_SMEM (3 * 64 * AST * 4)

__global__ void attn_tf32(const float* __restrict__ Q, const float* __restrict__ K,
                          const float* __restrict__ V, float* __restrict__ O) {
    extern __shared__ unsigned smu[];
    unsigned* Ks = smu;
    unsigned* Vs = Ks + 64 * AST;
    unsigned* Ps = Vs + 64 * AST;

    int bh = blockIdx.x, qt = blockIdx.y;
    int b = bh >> 4, h = bh & 15;
    int q0 = qt * 64;
    int tid = threadIdx.x, warp = tid >> 5, lane = tid & 31;
    int g = lane >> 2, tg = lane & 3;
    int r0l = warp * 16 + g;

    const float* Qb = Q + ((size_t)(b * TT + q0)) * DIMC + h * HD;
    const float* Kb = K + ((size_t)(b * TT)) * DIMC + h * HD;
    const float* Vb = V + ((size_t)(b * TT)) * DIMC + h * HD;

    unsigned qa[8][4];
    #pragma unroll
    for (int kt = 0; kt < 8; kt++) {
        qa[kt][0] = f2tf(Qb[(size_t)r0l * DIMC + kt * 8 + tg] * 0.125f);
        qa[kt][1] = f2tf(Qb[(size_t)(r0l + 8) * DIMC + kt * 8 + tg] * 0.125f);
        qa[kt][2] = f2tf(Qb[(size_t)r0l * DIMC + kt * 8 + tg + 4] * 0.125f);
        qa[kt][3] = f2tf(Qb[(size_t)(r0l + 8) * DIMC + kt * 8 + tg + 4] * 0.125f);
    }

    float oacc[8][4];
    #pragma unroll
    for (int nt = 0; nt < 8; nt++)
        #pragma unroll
        for (int r = 0; r < 4; r++) oacc[nt][r] = 0.f;
    float m0 = -1e30f, m1 = -1e30f, l0 = 0.f, l1 = 0.f;
    int r0g = q0 + r0l, r1g = r0g + 8;

    for (int s0 = 0; s0 <= q0; s0 += 64) {
        for (int i = tid; i < 1024; i += 128) {
            int r = i >> 4, c = (i & 15) << 2;
            float4 kv = *(const float4*)(Kb + (size_t)(s0 + r) * DIMC + c);
            unsigned* d = &Ks[r * AST + c];
            d[0] = f2tf(kv.x); d[1] = f2tf(kv.y); d[2] = f2tf(kv.z); d[3] = f2tf(kv.w);
            float4 vv = *(const float4*)(Vb + (size_t)(s0 + r) * DIMC + c);
            unsigned* e = &Vs[r * AST + c];
            e[0] = f2tf(vv.x); e[1] = f2tf(vv.y); e[2] = f2tf(vv.z); e[3] = f2tf(vv.w);
        }
        __syncthreads();

        float sc[8][4];
        #pragma unroll
        for (int nt = 0; nt < 8; nt++)
            #pragma unroll
            for (int r = 0; r < 4; r++) sc[nt][r] = 0.f;
        #pragma unroll
        for (int kk = 0; kk < 8; kk++) {
            #pragma unroll
            for (int nt = 0; nt < 8; nt++) {
                unsigned bf[2];
                const unsigned* p = &Ks[(nt * 8 + g) * AST + kk * 8 + tg];
                bf[0] = p[0];
                bf[1] = p[4];
                mma8(sc[nt], qa[kk], bf);
            }
        }

        if (s0 == q0) {
            #pragma unroll
            for (int nt = 0; nt < 8; nt++) {
                int j = s0 + nt * 8 + 2 * tg;
                if (j     > r0g) sc[nt][0] = -1e30f;
                if (j + 1 > r0g) sc[nt][1] = -1e30f;
                if (j     > r1g) sc[nt][2] = -1e30f;
                if (j + 1 > r1g) sc[nt][3] = -1e30f;
            }
        }

        float mx0 = -1e30f, mx1 = -1e30f;
        #pragma unroll
        for (int nt = 0; nt < 8; nt++) {
            mx0 = fmaxf(mx0, fmaxf(sc[nt][0], sc[nt][1]));
            mx1 = fmaxf(mx1, fmaxf(sc[nt][2], sc[nt][3]));
        }
        mx0 = fmaxf(mx0, __shfl_xor_sync(0xFFFFFFFFu, mx0, 1));
        mx0 = fmaxf(mx0, __shfl_xor_sync(0xFFFFFFFFu, mx0, 2));
        mx1 = fmaxf(mx1, __shfl_xor_sync(0xFFFFFFFFu, mx1, 1));
        mx1 = fmaxf(mx1, __shfl_xor_sync(0xFFFFFFFFu, mx1, 2));
        float mn0 = fmaxf(m0, mx0), mn1 = fmaxf(m1, mx1);
        float al0 = __expf(m0 - mn0), al1 = __expf(m1 - mn1);
        float s0r = 0.f, s1r = 0.f;
        #pragma unroll
        for (int nt = 0; nt < 8; nt++) {
            sc[nt][0] = __expf(sc[nt][0] - mn0);
            sc[nt][1] = __expf(sc[nt][1] - mn0);
            sc[nt][2] = __expf(sc[nt][2] - mn1);
            sc[nt][3] = __expf(sc[nt][3] - mn1);
            s0r += sc[nt][0] + sc[nt][1];
            s1r += sc[nt][2] + sc[nt][3];
        }
        s0r += __shfl_xor_sync(0xFFFFFFFFu, s0r, 1);
        s0r += __shfl_xor_sync(0xFFFFFFFFu, s0r, 2);
        s1r += __shfl_xor_sync(0xFFFFFFFFu, s1r, 1);
        s1r += __shfl_xor_sync(0xFFFFFFFFu, s1r, 2);
        l0 = l0 * al0 + s0r;
        l1 = l1 * al1 + s1r;
        m0 = mn0; m1 = mn1;
        #pragma unroll
        for (int nt = 0; nt < 8; nt++) {
            oacc[nt][0] *= al0; oacc[nt][1] *= al0;
            oacc[nt][2] *= al1; oacc[nt][3] *= al1;
        }

        #pragma unroll
        for (int nt = 0; nt < 8; nt++) {
            Ps[r0l * AST + nt * 8 + 2 * tg]           = f2tf(sc[nt][0]);
            Ps[r0l * AST + nt * 8 + 2 * tg + 1]       = f2tf(sc[nt][1]);
            Ps[(r0l + 8) * AST + nt * 8 + 2 * tg]     = f2tf(sc[nt][2]);
            Ps[(r0l + 8) * AST + nt * 8 + 2 * tg + 1] = f2tf(sc[nt][3]);
        }
        __syncwarp();
        unsigned pa[8][4];
        #pragma unroll
        for (int kt = 0; kt < 8; kt++) {
            const unsigned* p = &Ps[r0l * AST + kt * 8 + tg];
            pa[kt][0] = p[0];
            pa[kt][1] = p[8 * AST];
            pa[kt][2] = p[4];
            pa[kt][3] = p[8 * AST + 4];
        }

        #pragma unroll
        for (int kt = 0; kt < 8; kt++) {
            #pragma unroll
            for (int nt = 0; nt < 8; nt++) {
                unsigned bf[2];
                bf[0] = Vs[(kt * 8 + tg) * AST + nt * 8 + g];
                bf[1] = Vs[(kt * 8 + tg + 4) * AST + nt * 8 + g];
                mma8(oacc[nt], pa[kt], bf);
            }
        }
        __syncthreads();
    }

    float il0 = 1.f / l0, il1 = 1.f / l1;
    float* Ob = O + ((size_t)(b * TT + q0 + r0l)) * DIMC + h * HD;
    #pragma unroll
    for (int nt = 0; nt < 8; nt++) {
        *(float2*)(Ob + nt * 8 + 2 * tg) =
            make_float2(oacc[nt][0] * il0, oacc[nt][1] * il0);
        *(float2*)(Ob + (size_t)8 * DIMC + nt * 8 + 2 * tg) =
            make_float2(oacc[nt][2] * il1, oacc[nt][3] * il1);
    }
}

// ---------------- launcher ----------------------------------------------------
extern "C" void kernel_launch(void* const* d_in, const int* in_sizes, int n_in,
                              void* d_out, int out_size) {
    const float* x  = (const float*)d_in[0];
    const float* wq = (const float*)d_in[2];
    const float* wk = (const float*)d_in[3];
    const float* wv = (const float*)d_in[4];
    const float* wo = (const float*)d_in[5];
    const float* w1 = (const float*)d_in[6];
    const float* w2 = (const float*)d_in[7];
    const float* ga = (const float*)d_in[8];
    const float* gf = (const float*)d_in[9];
    float* out = (float*)d_out;

    float *xn, *q, *k, *v, *ao, *x1, *hb;
    cudaGetSymbolAddress((void**)&xn, g_xn);
    cudaGetSymbolAddress((void**)&q,  g_q);
    cudaGetSymbolAddress((void**)&k,  g_k);
    cudaGetSymbolAddress((void**)&v,  g_v);
    cudaGetSymbolAddress((void**)&ao, g_ao);
    cudaGetSymbolAddress((void**)&x1, g_x1);
    cudaGetSymbolAddress((void**)&hb, g_h);

    cudaFuncSetAttribute(gemm_tf32,
                         cudaFuncAttributeMaxDynamicSharedMemorySize, G_SMEM);
    cudaFuncSetAttribute(attn_tf32,
                         cudaFuncAttributeMaxDynamicSharedMemorySize, ATT_SMEM);

    dim3 gN1(DIMC / 128, BT / 128);   // (8, 32)
    dim3 gN4(HID  / 128, BT / 128);   // (32, 32)

    rmsnorm_kernel<<<BT, 256>>>(x, ga, xn);
    gemm_tf32<<<gN1, 256, G_SMEM>>>(xn, wq, q, nullptr, BT, DIMC, DIMC, 0);
    gemm_tf32<<<gN1, 256, G_SMEM>>>(xn, wk, k, nullptr, BT, DIMC, DIMC, 0);
    gemm_tf32<<<gN1, 256, G_SMEM>>>(xn, wv, v, nullptr, BT, DIMC, DIMC, 0);
    attn_tf32<<<dim3(BB * NH, TT / 64), 128, ATT_SMEM>>>(q, k, v, ao);
    gemm_tf32<<<gN1, 256, G_SMEM>>>(ao, wo, x1, x, BT, DIMC, DIMC, 0);
    rmsnorm_kernel<<<BT, 256>>>(x1, gf, xn);
    gemm_tf32<<<gN4, 256, G_SMEM>>>(xn, w1, hb, nullptr, BT, HID, DIMC, 1);
    gemm_tf32<<<gN1, 256, G_SMEM>>>(hb, w2, out, x1, BT, DIMC, HID, 0);
}